// round 8
// baseline (speedup 1.0000x reference)
#include <cuda_runtime.h>
#include <math.h>

// Problem shape (fixed by the dataset)
#define B_DIM 48
#define T_DIM 5000
#define F_DIM 161
#define BT (B_DIM * T_DIM)                  // 240000 rows
#define NEW_MAG_ELEMS ((size_t)BT * F_DIM)  // 38,640,000

#define CHUNK 100                   // frames per block
#define CHUNKS_PB (T_DIM / CHUNK)   // 50 chunks per batch
#define NBLK (B_DIM * CHUNKS_PB)    // 2400 blocks (~5.4 waves @ 3/SM)
#define THREADS 512
#define CHUNK_ELEMS (CHUNK * F_DIM) // 16100
#define CHUNK_F4 (CHUNK_ELEMS / 4)  // 4025 (exact; chunk base 16B-aligned)

// Dynamic smem: tile + ssum + sx + sA + sB  (sinv aliases ssum)
#define SMEM_FLOATS (CHUNK_ELEMS + 4 * CHUNK)
#define SMEM_BYTES (SMEM_FLOATS * 4)

// Scratch (no cudaMalloc): carry chain + ordering counter
__device__ float    g_carry[NBLK];
__device__ int      g_flag[NBLK];
__device__ unsigned g_counter;

__global__ void k_init() {
    int i = blockIdx.x * blockDim.x + threadIdx.x;
    if (i < NBLK) g_flag[i] = 0;
    if (i == 0) g_counter = 0u;
}

__global__ void __launch_bounds__(THREADS) k_fused(
    const float* __restrict__ mag,
    float* __restrict__ out,
    float* __restrict__ out_gain)
{
    extern __shared__ float smem[];
    float* tile = smem;                    // CHUNK_ELEMS
    float* ssum = smem + CHUNK_ELEMS;      // CHUNK (row square-sums; aliased sinv)
    float* sx   = ssum + CHUNK;            // CHUNK
    float* sA   = sx + CHUNK;              // CHUNK
    float* sB   = sA + CHUNK;              // CHUNK
    __shared__ unsigned s_vid;
    __shared__ float s_carry;

    int tid = threadIdx.x;
    int wid = tid >> 5, lane = tid & 31;

    if (tid == 0) s_vid = atomicAdd(&g_counter, 1u);
    if (tid < CHUNK) ssum[tid] = 0.0f;
    __syncthreads();
    unsigned vid = s_vid;
    int b = vid % B_DIM;        // chunk-major: all chunk-c blocks in same wave
    int c = vid / B_DIM;

    size_t row0 = (size_t)b * T_DIM + (size_t)c * CHUNK;
    const float* base = mag + row0 * F_DIM;

    // ---- pass 1: single DRAM read -> smem tile, square-sum fused in ----
    {
        const float4* m4 = (const float4*)base;
        float4* t4 = (float4*)tile;
        #pragma unroll 4
        for (int i = tid; i < CHUNK_F4; i += THREADS) {
            float4 v = m4[i];
            t4[i] = v;
            unsigned e0 = (unsigned)i * 4u;
            unsigned r0 = e0 / F_DIM;            // const-div -> mulhi
            unsigned rem = e0 - r0 * F_DIM;
            if (rem <= (unsigned)(F_DIM - 4)) {  // whole float4 in one row
                float s = fmaf(v.x, v.x, fmaf(v.y, v.y, fmaf(v.z, v.z, v.w * v.w)));
                atomicAdd(&ssum[r0], s);
            } else {                              // straddles row boundary
                float s0 = 0.0f, s1 = 0.0f;
                ((rem + 0 < F_DIM) ? s0 : s1) += v.x * v.x;
                ((rem + 1 < F_DIM) ? s0 : s1) += v.y * v.y;
                ((rem + 2 < F_DIM) ? s0 : s1) += v.z * v.z;
                ((rem + 3 < F_DIM) ? s0 : s1) += v.w * v.w;
                atomicAdd(&ssum[r0], s0);
                atomicAdd(&ssum[r0 + 1], s1);
            }
        }
    }
    __syncthreads();

    // ---- finish per-row power: sp = (2*sum - m0^2 - mN^2)/320 ----
    if (tid < CHUNK) {
        float sum = ssum[tid];
        float m0 = tile[tid * F_DIM];
        float mN = tile[tid * F_DIM + F_DIM - 1];
        float sp = (2.0f * sum - m0 * m0 - mN * mN) * (1.0f / 320.0f);
        sx[tid] = sqrtf(sp);
    }
    __syncthreads();

    // ---- warp 0: local affine scan over CHUNK rows; carry hop; publish ----
    if (wid == 0) {
        float cA = 1.0f, cB = 0.0f;
        int t_base = c * CHUNK;
        #pragma unroll
        for (int w = 0; w < (CHUNK + 31) / 32; w++) {
            int r = w * 32 + lane;
            float A, Bv;
            if (r < CHUNK) {
                float xv = sx[r];
                if (t_base + r == 0) { A = 0.0f; Bv = xv; }
                else                 { A = 0.9f; Bv = 0.1f * xv; }
            } else { A = 1.0f; Bv = 0.0f; }

            #pragma unroll
            for (int off = 1; off < 32; off <<= 1) {
                float Ap = __shfl_up_sync(0xffffffffu, A, off);
                float Bp = __shfl_up_sync(0xffffffffu, Bv, off);
                if (lane >= off) { Bv = fmaf(A, Bp, Bv); A *= Ap; }
            }
            float Apre = A * cA;
            float Bpre = fmaf(A, cB, Bv);
            if (r < CHUNK) { sA[r] = Apre; sB[r] = Bpre; }
            cA = __shfl_sync(0xffffffffu, Apre, 31);
            cB = __shfl_sync(0xffffffffu, Bpre, 31);
        }

        if (lane == 0) {
            float carry_in = 0.0f;
            int idx = b * CHUNKS_PB + c;
            if (c > 0) {
                // Atomic poll — never hoisted/elided by the compiler.
                while (atomicAdd(&g_flag[idx - 1], 0) == 0) {}
                __threadfence();
                carry_in = g_carry[idx - 1];
            }
            float carry_out = fmaf(cA, carry_in, cB);  // one FMA, then publish
            g_carry[idx] = carry_out;
            __threadfence();
            atomicExch(&g_flag[idx], 1);
            s_carry = carry_in;
        }
    }
    __syncthreads();
    float carry = s_carry;

    // ---- gains + reciprocals (sinv aliases ssum) ----
    float* sinv = ssum;
    float* og = out_gain + row0;
    if (tid < CHUNK) {
        float g = fmaf(sA[tid], carry, sB[tid]);
        og[tid] = g;
        sinv[tid] = 1.0f / (g + 0.001f);
    }
    __syncthreads();

    // ---- pass 2: new_mag = tile * inv (pure smem read), float4 stores ----
    {
        const float4* t4 = (const float4*)tile;
        float4* o4 = (float4*)(out + row0 * F_DIM);
        #pragma unroll 4
        for (int i = tid; i < CHUNK_F4; i += THREADS) {
            float4 v = t4[i];
            unsigned e0 = (unsigned)i * 4u;
            unsigned r0 = e0 / F_DIM;            // const-div -> mulhi
            unsigned rem = e0 - r0 * F_DIM;
            float inv0 = sinv[r0];
            float inv1 = (rem > (unsigned)(F_DIM - 4)) ? sinv[r0 + 1] : inv0;
            float4 rr;
            rr.x = v.x * inv0;
            rr.y = v.y * ((rem + 1 < F_DIM) ? inv0 : inv1);
            rr.z = v.z * ((rem + 2 < F_DIM) ? inv0 : inv1);
            rr.w = v.w * ((rem + 3 < F_DIM) ? inv0 : inv1);
            o4[i] = rr;
        }
    }
}

// ---------------------------------------------------------------------------
extern "C" void kernel_launch(void* const* d_in, const int* in_sizes, int n_in,
                              void* d_out, int out_size) {
    const float* mag = (const float*)d_in[0];
    float* out = (float*)d_out;
    float* out_gain = out + NEW_MAG_ELEMS;

    cudaFuncSetAttribute(k_fused, cudaFuncAttributeMaxDynamicSharedMemorySize,
                         SMEM_BYTES);

    k_init<<<(NBLK + 255) / 256, 256>>>();
    k_fused<<<NBLK, THREADS, SMEM_BYTES>>>(mag, out, out_gain);
}

// round 9
// speedup vs baseline: 1.9311x; 1.9311x over previous
#include <cuda_runtime.h>
#include <math.h>

// Problem shape (fixed by the dataset)
#define B_DIM 48
#define T_DIM 5000
#define F_DIM 161
#define BT (B_DIM * T_DIM)                  // 240000 rows
#define NEW_MAG_ELEMS ((size_t)BT * F_DIM)  // 38,640,000

#define CHUNK 200                  // frames per block (divides 5000, mult of 4)
#define CHUNKS_PB (T_DIM / CHUNK)  // 25 chunks per batch
#define NBLK (B_DIM * CHUNKS_PB)   // 1200 blocks
#define THREADS 512
#define CHUNK_ELEMS (CHUNK * F_DIM)  // 32200
#define CHUNK_F4 (CHUNK_ELEMS / 4)   // 8050 (exact; chunk base 16B-aligned)
#define NGROUPS (CHUNK / 4)          // 50 four-row groups, 161 float4s each

// Scratch (no cudaMalloc). Zero-initialized at module load; flags are
// consumed-and-reset by their single reader, so no init kernel is needed
// and the invariant holds across graph replays.
__device__ float    g_carry[NBLK];
__device__ int      g_flag[NBLK];
__device__ unsigned g_counter;

__global__ void __launch_bounds__(THREADS) k_fused(
    const float* __restrict__ mag,
    float* __restrict__ out,
    float* __restrict__ out_gain)
{
    __shared__ float sx[CHUNK];
    __shared__ float sA[CHUNK];
    __shared__ float sB[CHUNK];
    __shared__ float sinv[CHUNK];
    __shared__ unsigned s_vid;
    __shared__ float s_carry;

    int tid = threadIdx.x;
    int wid = tid >> 5, lane = tid & 31;

    if (tid == 0) s_vid = atomicAdd(&g_counter, 1u) % NBLK;
    __syncthreads();
    unsigned vid = s_vid;
    int b = vid % B_DIM;        // chunk-major: all chunk-c blocks in same wave
    int c = vid / B_DIM;

    size_t row0 = (size_t)b * T_DIM + (size_t)c * CHUNK;
    const float* base = mag + row0 * F_DIM;

    // ---- pass 1: per-4-row-group power, flat float4 loads (coalesced) ----
    // Group g = rows 4g..4g+3 = float4s [g*161, (g+1)*161), 16B-aligned.
    for (int g = wid; g < NGROUPS; g += THREADS / 32) {
        const float4* m4 = (const float4*)base + g * F_DIM;  // 161 float4s
        float s0 = 0.f, s1 = 0.f, s2 = 0.f, s3 = 0.f;
        #pragma unroll
        for (int it = 0; it < 6; it++) {
            int j = it * 32 + lane;
            if (j < F_DIM) {
                float4 v = m4[j];
                unsigned e = (unsigned)j * 4u;
                unsigned lr = e / F_DIM;               // 0..3 (const-div)
                unsigned rem = e - lr * F_DIM;
                float ax = v.x * v.x, ay = v.y * v.y;
                float az = v.z * v.z, aw = v.w * v.w;
                bool b1 = rem + 1 < F_DIM, b2 = rem + 2 < F_DIM, b3 = rem + 3 < F_DIM;
                float lo = ax + (b1 ? ay : 0.f) + (b2 ? az : 0.f) + (b3 ? aw : 0.f);
                float hi = (b1 ? 0.f : ay) + (b2 ? 0.f : az) + (b3 ? 0.f : aw);
                if      (lr == 0) { s0 += lo; s1 += hi; }
                else if (lr == 1) { s1 += lo; s2 += hi; }
                else if (lr == 2) { s2 += lo; s3 += hi; }
                else              { s3 += lo; }        // lr==3 never straddles
            }
        }
        #pragma unroll
        for (int off = 16; off > 0; off >>= 1) {
            s0 += __shfl_xor_sync(0xffffffffu, s0, off);
            s1 += __shfl_xor_sync(0xffffffffu, s1, off);
            s2 += __shfl_xor_sync(0xffffffffu, s2, off);
            s3 += __shfl_xor_sync(0xffffffffu, s3, off);
        }
        if (lane < 4) {
            float sum = (lane == 0) ? s0 : (lane == 1) ? s1 : (lane == 2) ? s2 : s3;
            int r = g * 4 + lane;
            float m0 = base[(size_t)r * F_DIM];            // L1 hits
            float mN = base[(size_t)r * F_DIM + F_DIM - 1];
            float sp = (2.0f * sum - m0 * m0 - mN * mN) * (1.0f / 320.0f);
            sx[r] = sqrtf(sp);
        }
    }
    __syncthreads();

    // ---- warp 0: local affine scan over CHUNK rows; carry hop; publish ----
    if (wid == 0) {
        float cA = 1.0f, cB = 0.0f;
        int t_base = c * CHUNK;
        #pragma unroll
        for (int w = 0; w < (CHUNK + 31) / 32; w++) {
            int r = w * 32 + lane;
            float A, Bv;
            if (r < CHUNK) {
                float xv = sx[r];
                if (t_base + r == 0) { A = 0.0f; Bv = xv; }
                else                 { A = 0.9f; Bv = 0.1f * xv; }
            } else { A = 1.0f; Bv = 0.0f; }

            #pragma unroll
            for (int off = 1; off < 32; off <<= 1) {
                float Ap = __shfl_up_sync(0xffffffffu, A, off);
                float Bp = __shfl_up_sync(0xffffffffu, Bv, off);
                if (lane >= off) { Bv = fmaf(A, Bp, Bv); A *= Ap; }
            }
            float Apre = A * cA;
            float Bpre = fmaf(A, cB, Bv);
            if (r < CHUNK) { sA[r] = Apre; sB[r] = Bpre; }
            cA = __shfl_sync(0xffffffffu, Apre, 31);
            cB = __shfl_sync(0xffffffffu, Bpre, 31);
        }

        if (lane == 0) {
            float carry_in = 0.0f;
            int idx = b * CHUNKS_PB + c;
            if (c > 0) {
                // Atomic poll — never hoisted/elided by the compiler.
                while (atomicAdd(&g_flag[idx - 1], 0) == 0) {}
                __threadfence();
                carry_in = g_carry[idx - 1];
                atomicExch(&g_flag[idx - 1], 0);   // self-clean for next replay
            }
            if (c < CHUNKS_PB - 1) {
                float carry_out = fmaf(cA, carry_in, cB);
                g_carry[idx] = carry_out;
                __threadfence();
                atomicExch(&g_flag[idx], 1);
            }
            s_carry = carry_in;
        }
    }
    __syncthreads();
    float carry = s_carry;

    // ---- gains + reciprocals ----
    float* og = out_gain + row0;
    for (int r = tid; r < CHUNK; r += THREADS) {
        float g = fmaf(sA[r], carry, sB[r]);
        og[r] = g;
        sinv[r] = 1.0f / (g + 0.001f);
    }
    __syncthreads();

    // ---- pass 2: new_mag = mag * inv; re-read hits L2 (evict-first) ----
    {
        const float4* m4 = (const float4*)base;
        float4* o4 = (float4*)(out + row0 * F_DIM);
        #pragma unroll 4
        for (int i = tid; i < CHUNK_F4; i += THREADS) {
            float4 v = __ldcs(&m4[i]);
            unsigned e0 = (unsigned)i * 4u;
            unsigned r0 = e0 / F_DIM;              // const-div -> mulhi
            unsigned rem = e0 - r0 * F_DIM;
            float inv0 = sinv[r0];
            float inv1 = (rem > (unsigned)(F_DIM - 4)) ? sinv[r0 + 1] : inv0;
            float4 rr;
            rr.x = v.x * inv0;
            rr.y = v.y * ((rem + 1 < F_DIM) ? inv0 : inv1);
            rr.z = v.z * ((rem + 2 < F_DIM) ? inv0 : inv1);
            rr.w = v.w * ((rem + 3 < F_DIM) ? inv0 : inv1);
            o4[i] = rr;
        }
    }
}

// ---------------------------------------------------------------------------
extern "C" void kernel_launch(void* const* d_in, const int* in_sizes, int n_in,
                              void* d_out, int out_size) {
    const float* mag = (const float*)d_in[0];
    float* out = (float*)d_out;
    float* out_gain = out + NEW_MAG_ELEMS;

    k_fused<<<NBLK, THREADS>>>(mag, out, out_gain);
}